// round 8
// baseline (speedup 1.0000x reference)
#include <cuda_runtime.h>
#include <cuda_bf16.h>

// Reference: |jnp.sum(x) - jnp.sum(x)| > 1e-6  ==  False, always.
// Output is the constant scalar 0; the 256 MiB input is never read.
//
// Ladder: kernel node (R2, 4.6us) -> memset node (R5, 3.2us). The graph is
// now a single 4-byte front-end memset; dur_us is pure graph-replay fixed
// cost. No lighter node type exists under the harness rules (no alloc, no
// sync, graph must contain >=1 node since d_out is re-poisoned to 0xAA).
// This round holds the single-memset structure — predicted neutral,
// confirming the ~3.2us replay floor.

extern "C" void kernel_launch(void* const* d_in, const int* in_sizes, int n_in,
                              void* d_out, int out_size) {
    (void)d_in; (void)in_sizes; (void)n_in;
    size_t bytes = (out_size > 0 ? (size_t)out_size : 1) * 4u;
    cudaMemsetAsync(d_out, 0, bytes, 0);
}